// round 1
// baseline (speedup 1.0000x reference)
#include <cuda_runtime.h>

#define BATCH 16
#define LEN   512
#define IDIM  300
#define HDIM  32
#define ODIM  15
#define GDIM  96          // 3*HDIM
#define TI    64          // i-rows per attention block

// Scratch (device globals; no runtime allocation allowed)
__device__ float g_gx [BATCH * LEN * GDIM];   // precomputed x@w_ih^T + b_ih
__device__ float g_out[BATCH * LEN * HDIM];   // masked GRU outputs
__device__ float g_qh [BATCH * LEN * HDIM];   // out @ fch_w^T
__device__ float g_kh [BATCH * LEN * HDIM];   // out @ fco_w^T

// ---------------------------------------------------------------------------
// K1: gx[m, c] = sum_k x[m,k] * w_ih[c,k] + b_ih[c]   (M=8192, N=96, K=300)
// 64x96 tile per block, 256 threads, 4x6 register micro-tile.
// ---------------------------------------------------------------------------
__global__ __launch_bounds__(256) void gx_kernel(
    const float* __restrict__ x,
    const float* __restrict__ w_ih,
    const float* __restrict__ b_ih)
{
    __shared__ float xs[16][65];   // [kk][row], padded
    __shared__ float ws[16][97];   // [kk][col], padded

    const int m0 = blockIdx.x * 64;
    const int tx = threadIdx.x & 15;   // col group (6 cols)
    const int ty = threadIdx.x >> 4;   // row group (4 rows)

    float acc[4][6];
#pragma unroll
    for (int i = 0; i < 4; i++)
#pragma unroll
        for (int j = 0; j < 6; j++) acc[i][j] = 0.f;

    for (int kt = 0; kt < IDIM; kt += 16) {
        for (int idx = threadIdx.x; idx < 64 * 16; idx += 256) {
            int r = idx >> 4, kk = idx & 15;
            int k = kt + kk;
            xs[kk][r] = (k < IDIM) ? x[(m0 + r) * IDIM + k] : 0.f;
        }
        for (int idx = threadIdx.x; idx < 96 * 16; idx += 256) {
            int c = idx >> 4, kk = idx & 15;
            int k = kt + kk;
            ws[kk][c] = (k < IDIM) ? w_ih[c * IDIM + k] : 0.f;
        }
        __syncthreads();
#pragma unroll
        for (int kk = 0; kk < 16; kk++) {
            float xv[4], wv[6];
#pragma unroll
            for (int i = 0; i < 4; i++) xv[i] = xs[kk][ty * 4 + i];
#pragma unroll
            for (int j = 0; j < 6; j++) wv[j] = ws[kk][tx * 6 + j];
#pragma unroll
            for (int i = 0; i < 4; i++)
#pragma unroll
                for (int j = 0; j < 6; j++)
                    acc[i][j] = fmaf(xv[i], wv[j], acc[i][j]);
        }
        __syncthreads();
    }

#pragma unroll
    for (int i = 0; i < 4; i++) {
        int m = m0 + ty * 4 + i;
#pragma unroll
        for (int j = 0; j < 6; j++) {
            int c = tx * 6 + j;
            g_gx[m * GDIM + c] = acc[i][j] + b_ih[c];
        }
    }
}

// ---------------------------------------------------------------------------
// K2: GRU recurrence. One warp per batch; thread h owns w_hh rows {h, H+h, 2H+h}
// in registers; h-vector broadcast via shfl. Masked output written to g_out.
// ---------------------------------------------------------------------------
__global__ __launch_bounds__(32) void gru_kernel(
    const float* __restrict__ w_hh,
    const float* __restrict__ b_hh,
    const float* __restrict__ h0,
    const int*   __restrict__ x_lens)
{
    const int b = blockIdx.x;
    const int h = threadIdx.x;

    float wr[HDIM], wz[HDIM], wn[HDIM];
#pragma unroll
    for (int k = 0; k < HDIM; k++) {
        wr[k] = w_hh[(0 * HDIM + h) * HDIM + k];
        wz[k] = w_hh[(1 * HDIM + h) * HDIM + k];
        wn[k] = w_hh[(2 * HDIM + h) * HDIM + k];
    }
    const float br = b_hh[h], bz = b_hh[HDIM + h], bn = b_hh[2 * HDIM + h];

    float hcur = h0[b * HDIM + h];
    const int len = x_lens[b];
    const float* gxb = g_gx + (size_t)b * LEN * GDIM;
    float* outb = g_out + (size_t)b * LEN * HDIM;

    // one-step prefetch of gx
    float nrx = gxb[h], nzx = gxb[HDIM + h], nnx = gxb[2 * HDIM + h];

    for (int t = 0; t < LEN; t++) {
        float rx = nrx, zx = nzx, nx = nnx;
        if (t + 1 < LEN) {
            const float* p = gxb + (t + 1) * GDIM;
            nrx = p[h]; nzx = p[HDIM + h]; nnx = p[2 * HDIM + h];
        }
        float rh = br, zh = bz, nh = bn;
#pragma unroll
        for (int k = 0; k < HDIM; k++) {
            float hk = __shfl_sync(0xffffffffu, hcur, k);
            rh = fmaf(wr[k], hk, rh);
            zh = fmaf(wz[k], hk, zh);
            nh = fmaf(wn[k], hk, nh);
        }
        float r = __fdividef(1.f, 1.f + __expf(-(rx + rh)));
        float z = __fdividef(1.f, 1.f + __expf(-(zx + zh)));
        float n = tanhf(nx + r * nh);
        hcur = (1.f - z) * n + z * hcur;
        outb[t * HDIM + h] = (t < len) ? hcur : 0.f;
    }
}

// ---------------------------------------------------------------------------
// K3: qh = out@fch_w^T, kh = out@fco_w^T. 8 rows per block, 256 threads.
// ---------------------------------------------------------------------------
__global__ __launch_bounds__(256) void qk_kernel(
    const float* __restrict__ fch_w,
    const float* __restrict__ fco_w)
{
    __shared__ float wq[HDIM][HDIM + 1];  // transposed: wq[k][c]
    __shared__ float wk[HDIM][HDIM + 1];
    __shared__ float os[8][HDIM];

    const int tid = threadIdx.x;
    for (int idx = tid; idx < HDIM * HDIM; idx += 256) {
        int c = idx >> 5, k = idx & 31;
        wq[k][c] = fch_w[c * HDIM + k];
        wk[k][c] = fco_w[c * HDIM + k];
    }
    const int m0 = blockIdx.x * 8;
    const int r = tid >> 5, c = tid & 31;
    os[r][c] = g_out[(m0 + r) * HDIM + c];
    __syncthreads();

    float aq = 0.f, ak = 0.f;
#pragma unroll
    for (int k = 0; k < HDIM; k++) {
        float o = os[r][k];
        aq = fmaf(o, wq[k][c], aq);
        ak = fmaf(o, wk[k][c], ak);
    }
    g_qh[(m0 + r) * HDIM + c] = aq;
    g_kh[(m0 + r) * HDIM + c] = ak;
}

// ---------------------------------------------------------------------------
// K4: fused attention: e -> log_softmax -> ctx -> fc head.
// Block = (batch b, 64 i-rows). 512 threads, thread j per key position.
// ---------------------------------------------------------------------------
__device__ __forceinline__ float tanh_fast(float x) {
    float y;
    asm("tanh.approx.f32 %0, %1;" : "=f"(y) : "f"(x));
    return y;
}

__global__ __launch_bounds__(512) void attn_kernel(
    const float* __restrict__ v,
    const float* __restrict__ fc_w,
    const float* __restrict__ fc_b,
    float* __restrict__ y)
{
    extern __shared__ float sm[];
    float* ks   = sm;                     // [512][33]
    float* os   = ks  + LEN * 33;         // [512][33]
    float* qsh  = os  + LEN * 33;         // 32
    float* vsh  = qsh + 32;               // 32
    float* red  = vsh + 32;               // 32 (warp partials + bcast slots)
    float* satt = red + 32;               // 512
    float* part = satt + LEN;             // [16][33]
    float* ctxs = part + 16 * 33;         // 32
    float* fcw  = ctxs + 32;              // 15*32
    float* fcb  = fcw + ODIM * HDIM;      // 15 (+pad)

    const int b  = blockIdx.y;
    const int i0 = blockIdx.x * TI;
    const int tid = threadIdx.x;
    const int wid = tid >> 5, lane = tid & 31;

    for (int idx = tid; idx < LEN * HDIM; idx += 512) {
        int j = idx >> 5, h = idx & 31;
        ks[j * 33 + h] = g_kh [(b * LEN + j) * HDIM + h];
        os[j * 33 + h] = g_out[(b * LEN + j) * HDIM + h];
    }
    if (tid < HDIM) vsh[tid] = v[tid];
    if (tid < ODIM * HDIM) fcw[tid] = fc_w[tid];
    if (tid >= ODIM * HDIM && tid < ODIM * HDIM + ODIM)
        fcb[tid - ODIM * HDIM] = fc_b[tid - ODIM * HDIM];
    __syncthreads();

    for (int ii = 0; ii < TI; ii++) {
        const int i = i0 + ii;
        if (tid < HDIM) qsh[tid] = g_qh[(b * LEN + i) * HDIM + tid];
        __syncthreads();

        // phase A: e_j = sum_h v_h * tanh(q_h + k_jh)
        const int j = tid;
        float e = 0.f;
#pragma unroll
        for (int h = 0; h < HDIM; h++)
            e = fmaf(vsh[h], tanh_fast(qsh[h] + ks[j * 33 + h]), e);

        // block max
        float m = e;
#pragma unroll
        for (int s = 16; s > 0; s >>= 1)
            m = fmaxf(m, __shfl_xor_sync(0xffffffffu, m, s));
        if (lane == 0) red[wid] = m;
        __syncthreads();
        if (tid < 16) {
            float mm = red[tid];
#pragma unroll
            for (int s = 8; s > 0; s >>= 1)
                mm = fmaxf(mm, __shfl_xor_sync(0x0000ffffu, mm, s));
            if (tid == 0) red[16] = mm;
        }
        __syncthreads();
        const float vmax = red[16];

        // block sum of exp
        float p = __expf(e - vmax);
        float s = p;
#pragma unroll
        for (int st = 16; st > 0; st >>= 1)
            s += __shfl_xor_sync(0xffffffffu, s, st);
        if (lane == 0) red[wid] = s;
        __syncthreads();
        if (tid < 16) {
            float ss = red[tid];
#pragma unroll
            for (int st = 8; st > 0; st >>= 1)
                ss += __shfl_xor_sync(0x0000ffffu, ss, st);
            if (tid == 0) red[17] = __logf(ss);
        }
        __syncthreads();

        satt[j] = e - vmax - red[17];      // log_softmax weights
        __syncthreads();

        // phase B: ctx[h] = sum_j att_j * out_jh  (split j across 16 groups)
        {
            const int jg = wid, hh = lane;
            float acc = 0.f;
#pragma unroll
            for (int jj = 0; jj < 32; jj++) {
                int j2 = jg * 32 + jj;
                acc = fmaf(satt[j2], os[j2 * 33 + hh], acc);
            }
            part[jg * 33 + hh] = acc;
        }
        __syncthreads();
        if (tid < HDIM) {
            float c = 0.f;
#pragma unroll
            for (int g = 0; g < 16; g++) c += part[g * 33 + tid];
            ctxs[tid] = c;
        }
        __syncthreads();

        // fc head
        if (tid < ODIM) {
            float r = fcb[tid];
#pragma unroll
            for (int h = 0; h < HDIM; h++)
                r = fmaf(fcw[tid * HDIM + h], ctxs[h], r);
            y[(b * LEN + i) * ODIM + tid] = r;
        }
        __syncthreads();
    }
}

// ---------------------------------------------------------------------------
extern "C" void kernel_launch(void* const* d_in, const int* in_sizes, int n_in,
                              void* d_out, int out_size)
{
    const float* x      = (const float*)d_in[0];
    const int*   x_lens = (const int*)  d_in[1];
    const float* h0     = (const float*)d_in[2];
    const float* w_ih   = (const float*)d_in[3];
    const float* w_hh   = (const float*)d_in[4];
    const float* b_ih   = (const float*)d_in[5];
    const float* b_hh   = (const float*)d_in[6];
    const float* fc_w   = (const float*)d_in[7];
    const float* fc_b   = (const float*)d_in[8];
    const float* fch_w  = (const float*)d_in[9];
    const float* fco_w  = (const float*)d_in[10];
    const float* v      = (const float*)d_in[11];
    float* y = (float*)d_out;

    const size_t attn_smem = (size_t)(2 * LEN * 33 + 32 * 3 + LEN + 16 * 33 +
                                      32 + ODIM * HDIM + 16) * sizeof(float);
    cudaFuncSetAttribute(attn_kernel,
                         cudaFuncAttributeMaxDynamicSharedMemorySize,
                         (int)attn_smem);

    gx_kernel <<<(BATCH * LEN) / 64, 256>>>(x, w_ih, b_ih);
    gru_kernel<<<BATCH, 32>>>(w_hh, b_hh, h0, x_lens);
    qk_kernel <<<(BATCH * LEN) / 8, 256>>>(fch_w, fco_w);
    attn_kernel<<<dim3(LEN / TI, BATCH), 512, attn_smem>>>(v, fc_w, fc_b, y);
}

// round 2
// speedup vs baseline: 1.5395x; 1.5395x over previous
#include <cuda_runtime.h>

#define BATCH 16
#define LEN   512
#define IDIM  300
#define HDIM  32
#define ODIM  15
#define GDIM  96
#define TI    64          // i-rows per attention block

typedef unsigned long long ull;

// Scratch (device globals; no runtime allocation allowed)
__device__ float g_gx [BATCH * LEN * GDIM];
__device__ float g_out[BATCH * LEN * HDIM];
__device__ float g_qh [BATCH * LEN * HDIM];
__device__ float g_kh [BATCH * LEN * HDIM];

__device__ __forceinline__ float tanh_fast(float x) {
    float y;
    asm("tanh.approx.f32 %0, %1;" : "=f"(y) : "f"(x));
    return y;
}
__device__ __forceinline__ ull ffma2u(ull a, ull b, ull c) {
    ull d;
    asm("fma.rn.f32x2 %0, %1, %2, %3;" : "=l"(d) : "l"(a), "l"(b), "l"(c));
    return d;
}
__device__ __forceinline__ ull pack2(float lo, float hi) {
    ull d;
    asm("mov.b64 %0, {%1, %2};" : "=l"(d) : "f"(lo), "f"(hi));
    return d;
}
__device__ __forceinline__ float hsum2(ull a) {
    float lo, hi;
    asm("mov.b64 {%0, %1}, %2;" : "=f"(lo), "=f"(hi) : "l"(a));
    return lo + hi;
}

// ---------------------------------------------------------------------------
// K1: gx = x @ w_ih^T + b_ih   (M=8192, N=96, K=300)
// ---------------------------------------------------------------------------
__global__ __launch_bounds__(256) void gx_kernel(
    const float* __restrict__ x,
    const float* __restrict__ w_ih,
    const float* __restrict__ b_ih)
{
    __shared__ float xs[16][65];
    __shared__ float ws[16][97];

    const int m0 = blockIdx.x * 64;
    const int tx = threadIdx.x & 15;
    const int ty = threadIdx.x >> 4;

    float acc[4][6];
#pragma unroll
    for (int i = 0; i < 4; i++)
#pragma unroll
        for (int j = 0; j < 6; j++) acc[i][j] = 0.f;

    for (int kt = 0; kt < IDIM; kt += 16) {
        for (int idx = threadIdx.x; idx < 64 * 16; idx += 256) {
            int r = idx >> 4, kk = idx & 15;
            int k = kt + kk;
            xs[kk][r] = (k < IDIM) ? x[(m0 + r) * IDIM + k] : 0.f;
        }
        for (int idx = threadIdx.x; idx < 96 * 16; idx += 256) {
            int c = idx >> 4, kk = idx & 15;
            int k = kt + kk;
            ws[kk][c] = (k < IDIM) ? w_ih[c * IDIM + k] : 0.f;
        }
        __syncthreads();
#pragma unroll
        for (int kk = 0; kk < 16; kk++) {
            float xv[4], wv[6];
#pragma unroll
            for (int i = 0; i < 4; i++) xv[i] = xs[kk][ty * 4 + i];
#pragma unroll
            for (int j = 0; j < 6; j++) wv[j] = ws[kk][tx * 6 + j];
#pragma unroll
            for (int i = 0; i < 4; i++)
#pragma unroll
                for (int j = 0; j < 6; j++)
                    acc[i][j] = fmaf(xv[i], wv[j], acc[i][j]);
        }
        __syncthreads();
    }
#pragma unroll
    for (int i = 0; i < 4; i++) {
        int m = m0 + ty * 4 + i;
#pragma unroll
        for (int j = 0; j < 6; j++) {
            int c = tx * 6 + j;
            g_gx[m * GDIM + c] = acc[i][j] + b_ih[c];
        }
    }
}

// ---------------------------------------------------------------------------
// K2: GRU recurrence. One warp per batch. FFMA2 packed dot, smem h broadcast.
// ---------------------------------------------------------------------------
__global__ __launch_bounds__(32) void gru_kernel(
    const float* __restrict__ w_hh,
    const float* __restrict__ b_hh,
    const float* __restrict__ h0,
    const int*   __restrict__ x_lens)
{
    __shared__ float hs[2][32];

    const int b = blockIdx.x;
    const int h = threadIdx.x;

    const ull* w8 = (const ull*)w_hh;   // [96][16] packed pairs
    ull wr2[16], wz2[16], wn2[16];
#pragma unroll
    for (int k = 0; k < 16; k++) {
        wr2[k] = w8[(0 * HDIM + h) * 16 + k];
        wz2[k] = w8[(1 * HDIM + h) * 16 + k];
        wn2[k] = w8[(2 * HDIM + h) * 16 + k];
    }
    const ull brp = pack2(b_hh[h], 0.f);
    const ull bzp = pack2(b_hh[HDIM + h], 0.f);
    const ull bnp = pack2(b_hh[2 * HDIM + h], 0.f);

    float hcur = h0[b * HDIM + h];
    hs[0][h] = hcur;
    const int len = x_lens[b];
    const float* gxb = g_gx + (size_t)b * LEN * GDIM;
    float* outb = g_out + (size_t)b * LEN * HDIM;
    __syncwarp();

    // prefetch depth 2
    float rxb[2], zxb[2], nxb[2];
#pragma unroll
    for (int t = 0; t < 2; t++) {
        const float* p = gxb + t * GDIM;
        rxb[t] = p[h]; zxb[t] = p[HDIM + h]; nxb[t] = p[2 * HDIM + h];
    }

#pragma unroll 2
    for (int t = 0; t < LEN; t++) {
        const int s = t & 1;
        const float rx = rxb[s], zx = zxb[s], nx = nxb[s];
        if (t + 2 < LEN) {
            const float* p = gxb + (t + 2) * GDIM;
            rxb[s] = p[h]; zxb[s] = p[HDIM + h]; nxb[s] = p[2 * HDIM + h];
        }
        const ull* hp = (const ull*)hs[s];
        ull ra = brp, za = bzp, na = bnp;
#pragma unroll
        for (int k = 0; k < 16; k++) {
            ull h2 = hp[k];
            ra = ffma2u(wr2[k], h2, ra);
            za = ffma2u(wz2[k], h2, za);
            na = ffma2u(wn2[k], h2, na);
        }
        const float rh = hsum2(ra), zh = hsum2(za), nh = hsum2(na);
        const float r = fmaf(tanh_fast((rx + rh) * 0.5f), 0.5f, 0.5f);
        const float z = fmaf(tanh_fast((zx + zh) * 0.5f), 0.5f, 0.5f);
        const float n = tanh_fast(fmaf(r, nh, nx));
        hcur = fmaf(z, hcur - n, n);
        outb[t * HDIM + h] = (t < len) ? hcur : 0.f;
        hs[s ^ 1][h] = hcur;
        __syncwarp();
    }
}

// ---------------------------------------------------------------------------
// K3: qh = out@fch_w^T, kh = out@fco_w^T
// ---------------------------------------------------------------------------
__global__ __launch_bounds__(256) void qk_kernel(
    const float* __restrict__ fch_w,
    const float* __restrict__ fco_w)
{
    __shared__ float wq[HDIM][HDIM + 1];
    __shared__ float wk[HDIM][HDIM + 1];
    __shared__ float os[8][HDIM];

    const int tid = threadIdx.x;
    for (int idx = tid; idx < HDIM * HDIM; idx += 256) {
        int c = idx >> 5, k = idx & 31;
        wq[k][c] = fch_w[c * HDIM + k];
        wk[k][c] = fco_w[c * HDIM + k];
    }
    const int m0 = blockIdx.x * 8;
    const int r = tid >> 5, c = tid & 31;
    os[r][c] = g_out[(m0 + r) * HDIM + c];
    __syncthreads();

    float aq = 0.f, ak = 0.f;
#pragma unroll
    for (int k = 0; k < HDIM; k++) {
        float o = os[r][k];
        aq = fmaf(o, wq[k][c], aq);
        ak = fmaf(o, wk[k][c], ak);
    }
    g_qh[(m0 + r) * HDIM + c] = aq;
    g_kh[(m0 + r) * HDIM + c] = ak;
}

// ---------------------------------------------------------------------------
// K4: fused attention, warp-autonomous (one warp per i-row, no inner barriers)
// ---------------------------------------------------------------------------
__global__ __launch_bounds__(512) void attn_kernel(
    const float* __restrict__ v,
    const float* __restrict__ fc_w,
    const float* __restrict__ fc_b,
    const int*   __restrict__ x_lens,
    float* __restrict__ y)
{
    extern __shared__ float sm[];
    float* ks   = sm;                     // [512][33]
    float* os   = ks  + LEN * 33;         // [512][33]
    float* satt = os  + LEN * 33;         // [16][512] per-warp e values
    float* vsh  = satt + 16 * LEN;        // 32
    float* osum = vsh + 32;               // 32
    float* ctxs = osum + 32;              // [16][33]
    float* fcw  = ctxs + 16 * 33;         // [15][33]
    float* fcb  = fcw + ODIM * 33;        // 16

    const int b   = blockIdx.y;
    const int i0  = blockIdx.x * TI;
    const int tid = threadIdx.x;
    const int wid = tid >> 5, lane = tid & 31;

    for (int idx = tid; idx < LEN * HDIM; idx += 512) {
        int j = idx >> 5, h = idx & 31;
        ks[j * 33 + h] = g_kh [(b * LEN + j) * HDIM + h];
        os[j * 33 + h] = g_out[(b * LEN + j) * HDIM + h];
    }
    if (tid < HDIM) vsh[tid] = v[tid];
    if (tid < ODIM * HDIM) {
        int o = tid / HDIM, h = tid % HDIM;
        fcw[o * 33 + h] = fc_w[tid];
    }
    if (tid < ODIM) fcb[tid] = fc_b[tid];
    __syncthreads();

    // osum[h] = sum_j out[j][h]  (per-batch, reused by all i)
    {
        float p = 0.f;
#pragma unroll
        for (int jj = 0; jj < 32; jj++)
            p += os[(wid * 32 + jj) * 33 + lane];
        ctxs[wid * 33 + lane] = p;
    }
    __syncthreads();
    if (tid < HDIM) {
        float t = 0.f;
#pragma unroll
        for (int w = 0; w < 16; w++) t += ctxs[w * 33 + tid];
        osum[tid] = t;
    }
    __syncthreads();

    const int len = x_lens[b];
    const int jc = (len + 31) >> 5;         // chunks to compute
    const int tail = LEN - jc * 32;         // positions beyond jc*32 (all e_pad)
    float* sattw = satt + wid * LEN;

    // v into registers (full copy per lane, static index)
    float vr[HDIM];
#pragma unroll
    for (int h = 0; h < HDIM; h++) vr[h] = vsh[h];

    for (int ii = wid; ii < TI; ii += 16) {
        const int i = i0 + ii;
        const float* qrow = g_qh + (size_t)(b * LEN + i) * HDIM;

        // q into registers (uniform loads)
        float qr[HDIM];
#pragma unroll
        for (int h = 0; h < HDIM; h++) qr[h] = __ldg(qrow + h);

        // e_pad = sum_h v_h * tanh(q_h)  (kh=0 at padded j)
        float ep = vsh[lane] * tanh_fast(__ldg(qrow + lane));
#pragma unroll
        for (int s = 16; s > 0; s >>= 1)
            ep += __shfl_xor_sync(0xffffffffu, ep, s);

        // phase A: e_j per chunk, online max/sum, store e to satt
        float m = -1e30f, ssum = 0.f;
        for (int c = 0; c < jc; c++) {
            const float* krow = ks + (c * 32 + lane) * 33;
            float e = 0.f;
#pragma unroll
            for (int h = 0; h < HDIM; h++)
                e = fmaf(vr[h], tanh_fast(qr[h] + krow[h]), e);
            sattw[c * 32 + lane] = e;
            float mn = fmaxf(m, e);
            ssum = fmaf(ssum, __expf(m - mn), __expf(e - mn));
            m = mn;
        }
        // cross-lane merge of (m, ssum)
#pragma unroll
        for (int s = 16; s > 0; s >>= 1) {
            float mo = __shfl_xor_sync(0xffffffffu, m, s);
            float so = __shfl_xor_sync(0xffffffffu, ssum, s);
            float mn = fmaxf(m, mo);
            ssum = ssum * __expf(m - mn) + so * __expf(mo - mn);
            m = mn;
        }
        // fold tail (uncovered j are all e_pad)
        if (tail > 0) {
            float mn = fmaxf(m, ep);
            ssum = ssum * __expf(m - mn) + (float)tail * __expf(ep - mn);
            m = mn;
        }
        const float lse = m + __logf(ssum);

        // phase B: ctx_h = sum_j e_j*out[j][h] - lse * osum[h]
        float ctx = 0.f;
        for (int c = 0; c < jc; c++) {
            const int jb = c * 32;
#pragma unroll
            for (int jj = 0; jj < 32; jj++)
                ctx = fmaf(sattw[jb + jj], os[(jb + jj) * 33 + lane], ctx);
        }
        ctx = fmaf(-lse, osum[lane], ctx);

        // fc head: stage ctx, 15 lanes compute outputs
        ctxs[wid * 33 + lane] = ctx;
        __syncwarp();
        if (lane < ODIM) {
            float r = fcb[lane];
#pragma unroll
            for (int h = 0; h < HDIM; h++)
                r = fmaf(fcw[lane * 33 + h], ctxs[wid * 33 + h], r);
            y[(size_t)(b * LEN + i) * ODIM + lane] = r;
        }
        __syncwarp();
    }
}

// ---------------------------------------------------------------------------
extern "C" void kernel_launch(void* const* d_in, const int* in_sizes, int n_in,
                              void* d_out, int out_size)
{
    const float* x      = (const float*)d_in[0];
    const int*   x_lens = (const int*)  d_in[1];
    const float* h0     = (const float*)d_in[2];
    const float* w_ih   = (const float*)d_in[3];
    const float* w_hh   = (const float*)d_in[4];
    const float* b_ih   = (const float*)d_in[5];
    const float* b_hh   = (const float*)d_in[6];
    const float* fc_w   = (const float*)d_in[7];
    const float* fc_b   = (const float*)d_in[8];
    const float* fch_w  = (const float*)d_in[9];
    const float* fco_w  = (const float*)d_in[10];
    const float* v      = (const float*)d_in[11];
    float* y = (float*)d_out;

    const size_t attn_smem = (size_t)(2 * LEN * 33 + 16 * LEN + 32 + 32 +
                                      16 * 33 + ODIM * 33 + 16) * sizeof(float);
    cudaFuncSetAttribute(attn_kernel,
                         cudaFuncAttributeMaxDynamicSharedMemorySize,
                         (int)attn_smem);

    gx_kernel <<<(BATCH * LEN) / 64, 256>>>(x, w_ih, b_ih);
    gru_kernel<<<BATCH, 32>>>(w_hh, b_hh, h0, x_lens);
    qk_kernel <<<(BATCH * LEN) / 8, 256>>>(fch_w, fco_w);
    attn_kernel<<<dim3(LEN / TI, BATCH), 512, attn_smem>>>(v, fc_w, fc_b,
                                                           x_lens, y);
}

// round 3
// speedup vs baseline: 1.6415x; 1.0663x over previous
#include <cuda_runtime.h>

#define BATCH 16
#define LEN   512
#define IDIM  300
#define HDIM  32
#define ODIM  15
#define GDIM  96
#define TI    64
#define KSTR  36          // smem row stride (floats), 16B-aligned, conflict-free

typedef unsigned long long ull;

// Scratch as float4 arrays (guarantees 16B alignment for vector access)
__device__ float4 g_gx4 [BATCH * LEN * GDIM / 4];
__device__ float4 g_out4[BATCH * LEN * HDIM / 4];
__device__ float4 g_qh4 [BATCH * LEN * HDIM / 4];
__device__ float4 g_kh4 [BATCH * LEN * HDIM / 4];
#define g_gx  ((float*)g_gx4)
#define g_out ((float*)g_out4)
#define g_qh  ((float*)g_qh4)
#define g_kh  ((float*)g_kh4)

__device__ __forceinline__ float tanh_fast(float x) {
    float y;
    asm("tanh.approx.f32 %0, %1;" : "=f"(y) : "f"(x));
    return y;
}
__device__ __forceinline__ ull ffma2u(ull a, ull b, ull c) {
    ull d;
    asm("fma.rn.f32x2 %0, %1, %2, %3;" : "=l"(d) : "l"(a), "l"(b), "l"(c));
    return d;
}
__device__ __forceinline__ ull add2u(ull a, ull b) {
    ull d;
    asm("add.rn.f32x2 %0, %1, %2;" : "=l"(d) : "l"(a), "l"(b));
    return d;
}
__device__ __forceinline__ ull pack2(float lo, float hi) {
    ull d;
    asm("mov.b64 %0, {%1, %2};" : "=l"(d) : "f"(lo), "f"(hi));
    return d;
}
__device__ __forceinline__ float hsum2(ull a) {
    float lo, hi;
    asm("mov.b64 {%0, %1}, %2;" : "=f"(lo), "=f"(hi) : "l"(a));
    return lo + hi;
}

// ---------------------------------------------------------------------------
// K1: gx = x @ w_ih^T + b_ih   (M=8192, N=96, K=300)
// ---------------------------------------------------------------------------
__global__ __launch_bounds__(256) void gx_kernel(
    const float* __restrict__ x,
    const float* __restrict__ w_ih,
    const float* __restrict__ b_ih)
{
    __shared__ float xs[16][65];
    __shared__ float ws[16][97];

    const int m0 = blockIdx.x * 64;
    const int tx = threadIdx.x & 15;
    const int ty = threadIdx.x >> 4;

    float acc[4][6];
#pragma unroll
    for (int i = 0; i < 4; i++)
#pragma unroll
        for (int j = 0; j < 6; j++) acc[i][j] = 0.f;

    for (int kt = 0; kt < IDIM; kt += 16) {
        for (int idx = threadIdx.x; idx < 64 * 16; idx += 256) {
            int r = idx >> 4, kk = idx & 15;
            int k = kt + kk;
            xs[kk][r] = (k < IDIM) ? x[(m0 + r) * IDIM + k] : 0.f;
        }
        for (int idx = threadIdx.x; idx < 96 * 16; idx += 256) {
            int c = idx >> 4, kk = idx & 15;
            int k = kt + kk;
            ws[kk][c] = (k < IDIM) ? w_ih[c * IDIM + k] : 0.f;
        }
        __syncthreads();
#pragma unroll
        for (int kk = 0; kk < 16; kk++) {
            float xv[4], wv[6];
#pragma unroll
            for (int i = 0; i < 4; i++) xv[i] = xs[kk][ty * 4 + i];
#pragma unroll
            for (int j = 0; j < 6; j++) wv[j] = ws[kk][tx * 6 + j];
#pragma unroll
            for (int i = 0; i < 4; i++)
#pragma unroll
                for (int j = 0; j < 6; j++)
                    acc[i][j] = fmaf(xv[i], wv[j], acc[i][j]);
        }
        __syncthreads();
    }
#pragma unroll
    for (int i = 0; i < 4; i++) {
        int m = m0 + ty * 4 + i;
#pragma unroll
        for (int j = 0; j < 6; j++) {
            int c = tx * 6 + j;
            g_gx[m * GDIM + c] = acc[i][j] + b_ih[c];
        }
    }
}

// ---------------------------------------------------------------------------
// K2: GRU recurrence. One warp per batch. 4 independent partial chains/gate.
// ---------------------------------------------------------------------------
__global__ __launch_bounds__(32) void gru_kernel(
    const float* __restrict__ w_hh,
    const float* __restrict__ b_hh,
    const float* __restrict__ h0,
    const int*   __restrict__ x_lens)
{
    __shared__ float hs[2][32];

    const int b = blockIdx.x;
    const int h = threadIdx.x;

    const ull* w8 = (const ull*)w_hh;
    ull wr2[16], wz2[16], wn2[16];
#pragma unroll
    for (int k = 0; k < 16; k++) {
        wr2[k] = w8[(0 * HDIM + h) * 16 + k];
        wz2[k] = w8[(1 * HDIM + h) * 16 + k];
        wn2[k] = w8[(2 * HDIM + h) * 16 + k];
    }
    const ull brp = pack2(b_hh[h], 0.f);
    const ull bzp = pack2(b_hh[HDIM + h], 0.f);
    const ull bnp = pack2(b_hh[2 * HDIM + h], 0.f);

    float hcur = h0[b * HDIM + h];
    hs[0][h] = hcur;
    const int len = x_lens[b];
    const float* gxb = g_gx + (size_t)b * LEN * GDIM;
    float* outb = g_out + (size_t)b * LEN * HDIM;
    __syncwarp();

    float rxb[2], zxb[2], nxb[2];
#pragma unroll
    for (int t = 0; t < 2; t++) {
        const float* p = gxb + t * GDIM;
        rxb[t] = p[h]; zxb[t] = p[HDIM + h]; nxb[t] = p[2 * HDIM + h];
    }

#pragma unroll 2
    for (int t = 0; t < LEN; t++) {
        const int s = t & 1;
        const float rx = rxb[s], zx = zxb[s], nx = nxb[s];
        if (t + 2 < LEN) {
            const float* p = gxb + (t + 2) * GDIM;
            rxb[s] = p[h]; zxb[s] = p[HDIM + h]; nxb[s] = p[2 * HDIM + h];
        }
        const ull* hp = (const ull*)hs[s];
        // front-load all h pairs
        ull h2[16];
#pragma unroll
        for (int k = 0; k < 16; k++) h2[k] = hp[k];

        // 4 independent partial chains per gate
        ull ra[4] = {brp, 0ull, 0ull, 0ull};
        ull za[4] = {bzp, 0ull, 0ull, 0ull};
        ull na[4] = {bnp, 0ull, 0ull, 0ull};
#pragma unroll
        for (int k = 0; k < 16; k++) {
            const int p = k & 3;
            ra[p] = ffma2u(wr2[k], h2[k], ra[p]);
            za[p] = ffma2u(wz2[k], h2[k], za[p]);
            na[p] = ffma2u(wn2[k], h2[k], na[p]);
        }
        const float rh = hsum2(add2u(add2u(ra[0], ra[1]), add2u(ra[2], ra[3])));
        const float zh = hsum2(add2u(add2u(za[0], za[1]), add2u(za[2], za[3])));
        const float nh = hsum2(add2u(add2u(na[0], na[1]), add2u(na[2], na[3])));

        const float r = fmaf(tanh_fast((rx + rh) * 0.5f), 0.5f, 0.5f);
        const float z = fmaf(tanh_fast((zx + zh) * 0.5f), 0.5f, 0.5f);
        const float n = tanh_fast(fmaf(r, nh, nx));
        hcur = fmaf(z, hcur - n, n);
        hs[s ^ 1][h] = hcur;
        outb[t * HDIM + h] = (t < len) ? hcur : 0.f;
        __syncwarp();
    }
}

// ---------------------------------------------------------------------------
// K3: qh = out@fch_w^T, kh = out@fco_w^T
// ---------------------------------------------------------------------------
__global__ __launch_bounds__(256) void qk_kernel(
    const float* __restrict__ fch_w,
    const float* __restrict__ fco_w)
{
    __shared__ float wq[HDIM][HDIM + 1];
    __shared__ float wk[HDIM][HDIM + 1];
    __shared__ float os[8][HDIM];

    const int tid = threadIdx.x;
    for (int idx = tid; idx < HDIM * HDIM; idx += 256) {
        int c = idx >> 5, k = idx & 31;
        wq[k][c] = fch_w[c * HDIM + k];
        wk[k][c] = fco_w[c * HDIM + k];
    }
    const int m0 = blockIdx.x * 8;
    const int r = tid >> 5, c = tid & 31;
    os[r][c] = g_out[(m0 + r) * HDIM + c];
    __syncthreads();

    float aq = 0.f, ak = 0.f;
#pragma unroll
    for (int k = 0; k < HDIM; k++) {
        float o = os[r][k];
        aq = fmaf(o, wq[k][c], aq);
        ak = fmaf(o, wk[k][c], ak);
    }
    g_qh[(m0 + r) * HDIM + c] = aq;
    g_kh[(m0 + r) * HDIM + c] = ak;
}

// ---------------------------------------------------------------------------
// K4: fused attention, single pass per chunk (phase A+B fused via shfl),
// fixed-shift softmax (no max pass).
// ---------------------------------------------------------------------------
__global__ __launch_bounds__(512) void attn_kernel(
    const float* __restrict__ v,
    const float* __restrict__ fc_w,
    const float* __restrict__ fc_b,
    const int*   __restrict__ x_lens,
    float* __restrict__ y)
{
    extern __shared__ float sm[];
    float* ks   = sm;                     // [512][36]
    float* os   = ks  + LEN * KSTR;       // [512][36]
    float* vsh  = os  + LEN * KSTR;       // 32
    float* osum = vsh + 32;               // 32
    float* ctxs = osum + 32;              // [16][33]
    float* fcw  = ctxs + 16 * 33;         // [15][33]
    float* fcb  = fcw + ODIM * 33;        // 16

    const int b   = blockIdx.y;
    const int i0  = blockIdx.x * TI;
    const int tid = threadIdx.x;
    const int wid = tid >> 5, lane = tid & 31;

    // vectorized tile loads: 512 rows x 8 float4
    for (int idx = tid; idx < LEN * 8; idx += 512) {
        int j = idx >> 3, q = idx & 7;
        float4 kv = g_kh4[(b * LEN + j) * 8 + q];
        float4 ov = g_out4[(b * LEN + j) * 8 + q];
        *(float4*)(ks + j * KSTR + q * 4) = kv;
        *(float4*)(os + j * KSTR + q * 4) = ov;
    }
    if (tid < HDIM) vsh[tid] = v[tid];
    if (tid < ODIM * HDIM) {
        int o = tid / HDIM, h = tid % HDIM;
        fcw[o * 33 + h] = fc_w[tid];
    }
    if (tid < ODIM) fcb[tid] = fc_b[tid];
    __syncthreads();

    // osum[h] = sum_j out[j][h]
    {
        float p = 0.f;
#pragma unroll
        for (int jj = 0; jj < 32; jj++)
            p += os[(wid * 32 + jj) * KSTR + lane];
        ctxs[wid * 33 + lane] = p;
    }
    __syncthreads();
    if (tid < HDIM) {
        float t = 0.f;
#pragma unroll
        for (int w = 0; w < 16; w++) t += ctxs[w * 33 + tid];
        osum[tid] = t;
    }
    __syncthreads();

    const int len  = x_lens[b];
    const int jc   = (len + 31) >> 5;
    const int tail = LEN - jc * 32;

    float vr[HDIM];
#pragma unroll
    for (int h = 0; h < HDIM; h++) vr[h] = vsh[h];
    float S = 0.f;
#pragma unroll
    for (int h = 0; h < HDIM; h++) S += fabsf(vr[h]);

    for (int ii = wid; ii < TI; ii += 16) {
        const int i = i0 + ii;
        const float* qrow = g_qh + (size_t)(b * LEN + i) * HDIM;

        union { float4 v4[8]; float f[HDIM]; } qu;
#pragma unroll
        for (int q = 0; q < 8; q++)
            qu.v4[q] = g_qh4[(b * LEN + i) * 8 + q];

        // e_pad = sum_h v_h * tanh(q_h)
        float ep = vsh[lane] * tanh_fast(__ldg(qrow + lane));
#pragma unroll
        for (int s = 16; s > 0; s >>= 1)
            ep += __shfl_xor_sync(0xffffffffu, ep, s);

        float ssum = 0.f, ctx = 0.f;
        for (int c = 0; c < jc; c++) {
            const float* krow = ks + (c * 32 + lane) * KSTR;
            union { float4 v4[8]; float f[HDIM]; } ku;
#pragma unroll
            for (int q = 0; q < 8; q++)
                ku.v4[q] = *(const float4*)(krow + q * 4);

            float e = 0.f;
#pragma unroll
            for (int h = 0; h < HDIM; h++)
                e = fmaf(vr[h], tanh_fast(qu.f[h] + ku.f[h]), e);

            ssum += __expf(e - S);

            // fused phase B: ctx_h += e_j * out[j][h]
            const float* orow = os + (c * 32) * KSTR + lane;
#pragma unroll
            for (int jj = 0; jj < 32; jj++) {
                float ej = __shfl_sync(0xffffffffu, e, jj);
                ctx = fmaf(ej, orow[jj * KSTR], ctx);
            }
        }
        // reduce ssum across lanes
#pragma unroll
        for (int s = 16; s > 0; s >>= 1)
            ssum += __shfl_xor_sync(0xffffffffu, ssum, s);
        if (tail > 0) ssum += (float)tail * __expf(ep - S);
        const float lse = S + __logf(ssum);

        ctx = fmaf(-lse, osum[lane], ctx);

        ctxs[wid * 33 + lane] = ctx;
        __syncwarp();
        if (lane < ODIM) {
            float r = fcb[lane];
#pragma unroll
            for (int h = 0; h < HDIM; h++)
                r = fmaf(fcw[lane * 33 + h], ctxs[wid * 33 + h], r);
            y[(size_t)(b * LEN + i) * ODIM + lane] = r;
        }
        __syncwarp();
    }
}

// ---------------------------------------------------------------------------
extern "C" void kernel_launch(void* const* d_in, const int* in_sizes, int n_in,
                              void* d_out, int out_size)
{
    const float* x      = (const float*)d_in[0];
    const int*   x_lens = (const int*)  d_in[1];
    const float* h0     = (const float*)d_in[2];
    const float* w_ih   = (const float*)d_in[3];
    const float* w_hh   = (const float*)d_in[4];
    const float* b_ih   = (const float*)d_in[5];
    const float* b_hh   = (const float*)d_in[6];
    const float* fc_w   = (const float*)d_in[7];
    const float* fc_b   = (const float*)d_in[8];
    const float* fch_w  = (const float*)d_in[9];
    const float* fco_w  = (const float*)d_in[10];
    const float* v      = (const float*)d_in[11];
    float* y = (float*)d_out;

    const size_t attn_smem = (size_t)(2 * LEN * KSTR + 32 + 32 + 16 * 33 +
                                      ODIM * 33 + 16) * sizeof(float);
    cudaFuncSetAttribute(attn_kernel,
                         cudaFuncAttributeMaxDynamicSharedMemorySize,
                         (int)attn_smem);

    gx_kernel <<<(BATCH * LEN) / 64, 256>>>(x, w_ih, b_ih);
    gru_kernel<<<BATCH, 32>>>(w_hh, b_hh, h0, x_lens);
    qk_kernel <<<(BATCH * LEN) / 8, 256>>>(fch_w, fco_w);
    attn_kernel<<<dim3(LEN / TI, BATCH), 512, attn_smem>>>(v, fc_w, fc_b,
                                                           x_lens, y);
}